// round 7
// baseline (speedup 1.0000x reference)
#include <cuda_runtime.h>

// Shapes: depth_map/x_ray [8,1,512,512] fp32 -> out [8,1,128,128,128] fp32
#define NB   8
#define INHW 512
#define RHW  128   // resized H=W
#define ND   128   // depth bins

// Intermediate buffers (device globals: allocation-free scratch)
__device__ float g_xr[NB * RHW * RHW];
__device__ int   g_di[NB * RHW * RHW];

// ---------------------------------------------------------------------------
// Kernel 1: jax.image.resize(bilinear, antialias=True) 512->128 both arrays,
// plus depth->index conversion. Block = (h_out, b), 128 threads; each thread
// owns 4 consecutive input columns (float4) for the vertical pass, then one
// output pixel for the horizontal pass. Raw triangle weights
// {1,3,5,7,7,5,3,1}/8, normalized by the in-range weight sum.
// ---------------------------------------------------------------------------
__global__ __launch_bounds__(128) void resize_kernel(const float* __restrict__ depth,
                                                     const float* __restrict__ xray) {
    const int h   = blockIdx.x;
    const int b   = blockIdx.y;
    const int tid = threadIdx.x;

    __shared__ float tmpd[INHW];
    __shared__ float tmpx[INHW];

    const float RW[8] = {0.125f, 0.375f, 0.625f, 0.875f,
                         0.875f, 0.625f, 0.375f, 0.125f};

    float4 ad = make_float4(0.f, 0.f, 0.f, 0.f);
    float4 ax = make_float4(0.f, 0.f, 0.f, 0.f);
    float wsv = 0.f;

    #pragma unroll
    for (int t = 0; t < 8; ++t) {
        int j = 4 * h - 2 + t;                 // input row (uniform per block)
        if ((unsigned)j >= (unsigned)INHW) continue;
        float wv = RW[t];
        wsv += wv;
        const float4* drow = (const float4*)(depth + ((size_t)b * INHW + j) * INHW);
        const float4* xrow = (const float4*)(xray  + ((size_t)b * INHW + j) * INHW);
        float4 dv = drow[tid];
        float4 xv = xrow[tid];
        ad.x = fmaf(wv, dv.x, ad.x); ad.y = fmaf(wv, dv.y, ad.y);
        ad.z = fmaf(wv, dv.z, ad.z); ad.w = fmaf(wv, dv.w, ad.w);
        ax.x = fmaf(wv, xv.x, ax.x); ax.y = fmaf(wv, xv.y, ax.y);
        ax.z = fmaf(wv, xv.z, ax.z); ax.w = fmaf(wv, xv.w, ax.w);
    }
    ((float4*)tmpd)[tid] = ad;
    ((float4*)tmpx)[tid] = ax;
    __syncthreads();

    float sd = 0.f, sx = 0.f, wsh = 0.f;
    #pragma unroll
    for (int t = 0; t < 8; ++t) {
        int c = 4 * tid - 2 + t;               // input col
        if ((unsigned)c < (unsigned)INHW) {
            float wv = RW[t];
            wsh += wv;
            sd = fmaf(wv, tmpd[c], sd);
            sx = fmaf(wv, tmpx[c], sx);
        }
    }
    float inv = 1.f / (wsv * wsh);
    float dv  = sd * inv;                      // resized depth
    float xv  = sx * inv;                      // resized x_ray

    // d_idx = clip(int((depth/100)*127), 0, 127)  (truncation; depth >= 0)
    int di = (int)((dv / 100.f) * 127.f);
    di = di < 0 ? 0 : (di > ND - 1 ? ND - 1 : di);

    int idx = (b * RHW + h) * RHW + tid;
    g_xr[idx] = xv;
    g_di[idx] = di;
}

// ---------------------------------------------------------------------------
// Kernel 2: fused gaussian depth splat + 3x3x3 avg pool (/27, include_pad).
// Block = (h, b), 512 threads = (w = tid&127, g = tid>>7). Group g owns the
// 32-depth window [32g, 32g+32) of every column. 64KB dynamic smem holds the
// 128(d) x 128(w) tile d-major: thread w always hits bank w%32 -> zero
// conflicts for zeroing, scatter-adds, and the coalesced output stores.
// Each (d,w) cell is written by exactly one thread -> no atomics, and no
// syncthreads needed between accumulate and readout.
// Each of the 9 spatial neighbors contributes a <=7-wide depth bump around
// its d_idx; a thread first interval-tests the bump against its window
// (hit ~30%) before doing the 7-tap work.
// ---------------------------------------------------------------------------
__global__ __launch_bounds__(512) void splat_pool_kernel(float* __restrict__ out) {
    extern __shared__ float vol[];             // [128 d][128 w], d-major, 64KB
    __shared__ float sxs[3][130];
    __shared__ int   sdis[3][130];

    const int h   = blockIdx.x;
    const int b   = blockIdx.y;
    const int tid = threadIdx.x;
    const int w   = tid & 127;
    const int g   = tid >> 7;
    const int d0  = g << 5;                    // this thread's depth window base

    // Cooperative halo load: 3 rows x 130 cols (zero-padded out of range)
    if (tid < 3 * 130) {
        int dh = tid / 130, wi = tid - dh * 130;
        int hh = h + dh - 1, ww = wi - 1;
        bool v = ((unsigned)hh < (unsigned)RHW) && ((unsigned)ww < (unsigned)RHW);
        int idx = (b * RHW + (v ? hh : 0)) * RHW + (v ? ww : 0);
        sxs[dh][wi]  = v ? g_xr[idx] : 0.f;
        sdis[dh][wi] = v ? g_di[idx] : 0;
    }
    #pragma unroll
    for (int r = 0; r < 32; ++r) vol[(d0 + r) * 128 + w] = 0.f;
    __syncthreads();

    const float gw[5] = {0.13533528324f,   // exp(-2)
                         0.60653065971f,   // exp(-0.5)
                         1.0f,
                         0.60653065971f,
                         0.13533528324f};

    #pragma unroll
    for (int dh = 0; dh < 3; ++dh) {
        #pragma unroll
        for (int dw = 0; dw < 3; ++dw) {
            float xv = sxs[dh][w + dw];
            if (xv == 0.f) continue;           // padding (or exact-zero: no-op)
            int di = sdis[dh][w + dw];
            // bump covers depths [di-3, di+3]; skip if it misses our window
            if (di < d0 - 3 || di > d0 + 34) continue;

            float bump[7] = {0.f, 0.f, 0.f, 0.f, 0.f, 0.f, 0.f};
            #pragma unroll
            for (int o = 0; o < 5; ++o) {
                int dt = di + o - 2;           // splat target
                if ((unsigned)dt < (unsigned)ND) {
                    float v = gw[o];
                    bump[o]     += v;          // pooled to dt-1
                    bump[o + 1] += v;          // pooled to dt
                    bump[o + 2] += v;          // pooled to dt+1
                }
            }
            #pragma unroll
            for (int t = 0; t < 7; ++t) {
                int d = di + t - 3;
                if ((unsigned)(d - d0) < 32u)  // in window (handles d<0 too)
                    vol[d * 128 + w] += xv * bump[t];
            }
        }
    }
    // No sync: this thread reads only the cells it wrote.

    const float inv27 = 1.0f / 27.0f;
    float* obase = out + (size_t)b * (ND * RHW * RHW) + (size_t)h * RHW + w;
    #pragma unroll
    for (int r = 0; r < 32; ++r) {
        int d = d0 + r;
        obase[(size_t)d * (RHW * RHW)] = vol[d * 128 + w] * inv27;
    }
}

// ---------------------------------------------------------------------------
extern "C" void kernel_launch(void* const* d_in, const int* in_sizes, int n_in,
                              void* d_out, int out_size) {
    const float* depth = (const float*)d_in[0];   // [8,1,512,512] fp32
    const float* xray  = (const float*)d_in[1];   // [8,1,512,512] fp32
    float* out = (float*)d_out;                   // [8,1,128,128,128] fp32

    (void)in_sizes; (void)n_in; (void)out_size;

    // 64KB dynamic smem for the column tile (above the 48KB default cap).
    cudaFuncSetAttribute(splat_pool_kernel,
                         cudaFuncAttributeMaxDynamicSharedMemorySize, 65536);

    dim3 grid(RHW, NB);
    resize_kernel<<<grid, 128>>>(depth, xray);
    splat_pool_kernel<<<grid, 128 * 4, 65536>>>(out);
}